// round 4
// baseline (speedup 1.0000x reference)
#include <cuda_runtime.h>
#include <cstdint>

#define B_ 64
#define T_ 2048
#define I_ 512
#define H_ 1024
#define MTOT (B_ * T_)                 // 131072 rows for the projection GEMM
#define BSTRIDE ((size_t)T_ * H_)      // stride between batch rows in out
#define NBLK 128                       // persistent-kernel grid (16 n-tiles x 8 k-slabs)

// Scratch: Uw transposed to [k][n] so recurrence B-operand loads are row-contiguous.
__device__ float g_UwT[H_ * H_];
// Grid-barrier arrival counter for the persistent recurrence kernel.
__device__ unsigned g_bar;

// ---------------------------------------------------------------------------
// Transpose Uw[n][k] (row-major) -> g_UwT[k][n]; also reset the grid barrier.
// ---------------------------------------------------------------------------
__global__ __launch_bounds__(256) void uw_transpose_kernel(const float* __restrict__ Uw) {
    if (blockIdx.x == 0 && blockIdx.y == 0 && threadIdx.x == 0) g_bar = 0u;
    __shared__ float tile[32][33];
    const int bx = blockIdx.x * 32;   // k block (source column)
    const int by = blockIdx.y * 32;   // n block (source row)
    const int tx = threadIdx.x & 31;
    const int tw = threadIdx.x >> 5;  // 0..7
#pragma unroll
    for (int r = 0; r < 32; r += 8)
        tile[tw + r][tx] = Uw[(size_t)(by + tw + r) * H_ + bx + tx];
    __syncthreads();
#pragma unroll
    for (int r = 0; r < 32; r += 8)
        g_UwT[(size_t)(bx + tw + r) * H_ + by + tx] = tile[tx][tw + r];
}

// ---------------------------------------------------------------------------
// Projection: out[m][n] = sum_k x[m][k] * W[n][k] + Ub[n] + b[n]
// M = 131072, N = 1024, K = 512. 128x128 block tile, BK=16, 8x8 micro-tile.
// ---------------------------------------------------------------------------
__global__ __launch_bounds__(256) void proj_kernel(
    const float* __restrict__ x, const float* __restrict__ W,
    const float* __restrict__ Ub, const float* __restrict__ bvec,
    float* __restrict__ out)
{
    __shared__ float As[16][128];
    __shared__ float Bs[16][128];
    const int tid = threadIdx.x;
    const int m0 = blockIdx.y * 128;
    const int n0 = blockIdx.x * 128;
    const int ty = tid >> 4;   // 0..15
    const int tx = tid & 15;   // 0..15

    float acc[8][8];
#pragma unroll
    for (int i = 0; i < 8; i++)
#pragma unroll
        for (int j = 0; j < 8; j++) acc[i][j] = 0.f;

    for (int kb = 0; kb < I_; kb += 16) {
#pragma unroll
        for (int l = 0; l < 2; l++) {
            int idx = tid + l * 256;        // 0..511
            int row = idx >> 2;             // 0..127
            int c4  = (idx & 3) << 2;       // 0,4,8,12
            float4 av = *(const float4*)(x + (size_t)(m0 + row) * I_ + kb + c4);
            As[c4 + 0][row] = av.x; As[c4 + 1][row] = av.y;
            As[c4 + 2][row] = av.z; As[c4 + 3][row] = av.w;
            float4 wv = *(const float4*)(W + (size_t)(n0 + row) * I_ + kb + c4);
            Bs[c4 + 0][row] = wv.x; Bs[c4 + 1][row] = wv.y;
            Bs[c4 + 2][row] = wv.z; Bs[c4 + 3][row] = wv.w;
        }
        __syncthreads();
#pragma unroll
        for (int k = 0; k < 16; k++) {
            float a[8], bb[8];
            *(float4*)&a[0]  = *(const float4*)&As[k][ty * 8];
            *(float4*)&a[4]  = *(const float4*)&As[k][ty * 8 + 4];
            *(float4*)&bb[0] = *(const float4*)&Bs[k][tx * 8];
            *(float4*)&bb[4] = *(const float4*)&Bs[k][tx * 8 + 4];
#pragma unroll
            for (int i = 0; i < 8; i++)
#pragma unroll
                for (int j = 0; j < 8; j++) acc[i][j] += a[i] * bb[j];
        }
        __syncthreads();
    }

    float ubb[8];
#pragma unroll
    for (int j = 0; j < 8; j++) {
        int n = n0 + tx * 8 + j;
        ubb[j] = Ub[n] + bvec[n];
    }
#pragma unroll
    for (int i = 0; i < 8; i++) {
        float* dst = out + (size_t)(m0 + ty * 8 + i) * H_ + n0 + tx * 8;
        float4 v0 = make_float4(acc[i][0] + ubb[0], acc[i][1] + ubb[1],
                                acc[i][2] + ubb[2], acc[i][3] + ubb[3]);
        float4 v1 = make_float4(acc[i][4] + ubb[4], acc[i][5] + ubb[5],
                                acc[i][6] + ubb[6], acc[i][7] + ubb[7]);
        *(float4*)dst       = v0;
        *(float4*)(dst + 4) = v1;
    }
}

// ---------------------------------------------------------------------------
// Persistent recurrence kernel: runs ALL 2047 steps internally.
//   out[b][t][n] += sum_k out[b][t-1][k] * Uw[n][k]
// Grid = 128 blocks: (bid & 15) -> n-tile (64 cols), (bid >> 4) -> k-slab (128).
// Each block preloads its UwT slab into smem ONCE (reused for all steps).
// Per step: stage prev state slab -> smem, FFMA 64x64x128 partial,
// red.v4.f32 merge onto wx in d_out, then grid barrier.
// ---------------------------------------------------------------------------
__global__ __launch_bounds__(256) void rnn_persistent_kernel(float* __restrict__ out)
{
    __shared__ float Ss[64][132];    // [b][k-slab], padded
    __shared__ float Us[128][64];    // [k-slab][n-tile]
    const int tid = threadIdx.x;
    const int bid = blockIdx.x;
    const int n0 = (bid & 15) * 64;
    const int k0 = (bid >> 4) * 128;
    const int ty = tid >> 4;         // 0..15 -> b-quad
    const int tx = tid & 15;         // 0..15 -> n-quad

    // Preload UwT slab (128 x 64 floats) once.
#pragma unroll
    for (int l = 0; l < 8; l++) {
        int idx = tid + l * 256;     // 0..2047
        int r  = idx >> 4;           // 0..127 (k)
        int c4 = (idx & 15) << 2;    // 0..60  (n)
        *(float4*)&Us[r][c4] =
            *(const float4*)(g_UwT + (size_t)(k0 + r) * H_ + n0 + c4);
    }
    __syncthreads();

    for (int t = 1; t < T_; t++) {
        // Stage prev state slab: out[b][t-1][k0 : k0+128]  (64 x 128 floats)
        const float* prev = out + (size_t)(t - 1) * H_ + k0;
#pragma unroll
        for (int l = 0; l < 8; l++) {
            int idx = tid + l * 256;   // 0..2047
            int b   = idx >> 5;        // 0..63
            int c4  = (idx & 31) << 2; // 0..124
            *(float4*)&Ss[b][c4] =
                *(const float4*)(prev + (size_t)b * BSTRIDE + c4);
        }
        __syncthreads();

        float acc[4][4];
#pragma unroll
        for (int i = 0; i < 4; i++)
#pragma unroll
            for (int j = 0; j < 4; j++) acc[i][j] = 0.f;

#pragma unroll 8
        for (int k = 0; k < 128; k++) {
            float4 bv = *(const float4*)&Us[k][tx * 4];
            float a0 = Ss[ty * 4 + 0][k];
            float a1 = Ss[ty * 4 + 1][k];
            float a2 = Ss[ty * 4 + 2][k];
            float a3 = Ss[ty * 4 + 3][k];
            acc[0][0] += a0 * bv.x; acc[0][1] += a0 * bv.y; acc[0][2] += a0 * bv.z; acc[0][3] += a0 * bv.w;
            acc[1][0] += a1 * bv.x; acc[1][1] += a1 * bv.y; acc[1][2] += a1 * bv.z; acc[1][3] += a1 * bv.w;
            acc[2][0] += a2 * bv.x; acc[2][1] += a2 * bv.y; acc[2][2] += a2 * bv.z; acc[2][3] += a2 * bv.w;
            acc[3][0] += a3 * bv.x; acc[3][1] += a3 * bv.y; acc[3][2] += a3 * bv.z; acc[3][3] += a3 * bv.w;
        }

        // Merge partials onto wx already resident at out[:, t, :].
#pragma unroll
        for (int i = 0; i < 4; i++) {
            float* dst = out + (size_t)(ty * 4 + i) * BSTRIDE
                             + (size_t)t * H_ + n0 + tx * 4;
            asm volatile("red.global.add.v4.f32 [%0], {%1,%2,%3,%4};"
                         :: "l"(dst), "f"(acc[i][0]), "f"(acc[i][1]),
                            "f"(acc[i][2]), "f"(acc[i][3])
                         : "memory");
        }

        // Grid barrier: all blocks' REDs into out[:, t, :] must be visible
        // before any block stages out[:, t, :] as prev state of step t+1.
        if (t < T_ - 1) {
            __threadfence();   // order REDs before arrive
            if (tid == 0) {
                unsigned target = (unsigned)t * NBLK;
                atomicAdd(&g_bar, 1u);
                unsigned v;
                do {
                    asm volatile("ld.acquire.gpu.global.u32 %0, [%1];"
                                 : "=r"(v) : "l"(&g_bar));
                } while (v < target);
            }
            __syncthreads();   // broadcast barrier pass + order with acquire
        }
    }
}

// ---------------------------------------------------------------------------
extern "C" void kernel_launch(void* const* d_in, const int* in_sizes, int n_in,
                              void* d_out, int out_size) {
    (void)in_sizes; (void)n_in; (void)out_size;
    const float* x   = (const float*)d_in[0];
    const float* W   = (const float*)d_in[1];
    const float* Uw  = (const float*)d_in[2];
    const float* Ub  = (const float*)d_in[3];
    const float* bv  = (const float*)d_in[4];
    float* out = (float*)d_out;

    // 1) transpose Uw -> g_UwT and reset barrier counter
    uw_transpose_kernel<<<dim3(H_ / 32, H_ / 32), 256>>>(Uw);

    // 2) wx = x @ W^T + Ub + b   (writes all of out; t=0 row is the t=0 state)
    proj_kernel<<<dim3(H_ / 128, MTOT / 128), 256>>>(x, W, Ub, bv, out);

    // 3) all 2047 recurrence steps in ONE persistent kernel (3 graph nodes total)
    rnn_persistent_kernel<<<NBLK, 256>>>(out);
}

// round 10
// speedup vs baseline: 1.0047x; 1.0047x over previous
#include <cuda_runtime.h>
#include <cstdint>

#define B_ 64
#define T_ 2048
#define I_ 512
#define H_ 1024
#define MTOT (B_ * T_)
#define BSTRIDE ((size_t)T_ * H_)   // stride between batch rows in out
#define NBLK 128                    // persistent grid: 16 n-tiles x 8 k-slabs
#define PKP2 36                     // proj padded k-row (32+4 fp32 words): 36%32=4 -> conflict-free

// Scratch: Uw transposed to [k][n] for the fp32 recurrence (validated in R4).
__device__ float g_UwT[H_ * H_];
__device__ unsigned g_bar;          // grid-barrier arrival counter

// ---------------------------------------------------------------------------
// helpers
// ---------------------------------------------------------------------------
__device__ __forceinline__ uint32_t f2tf32(float x) {
    uint32_t u;
    asm("cvt.rna.tf32.f32 %0, %1;" : "=r"(u) : "f"(x));
    return u;
}
__device__ __forceinline__ void mma_tf32(float* d, const uint32_t* a, const uint32_t* b) {
    asm volatile(
        "mma.sync.aligned.m16n8k8.row.col.f32.tf32.tf32.f32 "
        "{%0,%1,%2,%3}, {%4,%5,%6,%7}, {%8,%9}, {%0,%1,%2,%3};"
        : "+f"(d[0]), "+f"(d[1]), "+f"(d[2]), "+f"(d[3])
        : "r"(a[0]), "r"(a[1]), "r"(a[2]), "r"(a[3]), "r"(b[0]), "r"(b[1]));
}
// 2-way tf32 split: x = hi + lo + delta, |delta| <= 2^-22 |x|.
__device__ __forceinline__ void split4(float* hi, float* lo, float4 v) {
    float f[4] = {v.x, v.y, v.z, v.w};
    float h[4], l[4];
#pragma unroll
    for (int i = 0; i < 4; i++) {
        h[i] = __uint_as_float(f2tf32(f[i]));
        l[i] = __uint_as_float(f2tf32(f[i] - h[i]));
    }
    *(float4*)hi = make_float4(h[0], h[1], h[2], h[3]);
    *(float4*)lo = make_float4(l[0], l[1], l[2], l[3]);
}

// ---------------------------------------------------------------------------
// Transpose Uw[n][k] -> g_UwT[k][n]; also reset the grid barrier. (R4-validated)
// ---------------------------------------------------------------------------
__global__ __launch_bounds__(256) void uw_transpose_kernel(const float* __restrict__ Uw) {
    if (blockIdx.x == 0 && blockIdx.y == 0 && threadIdx.x == 0) g_bar = 0u;
    __shared__ float tile[32][33];
    const int bx = blockIdx.x * 32;   // k block (source column)
    const int by = blockIdx.y * 32;   // n block (source row)
    const int tx = threadIdx.x & 31;
    const int tw = threadIdx.x >> 5;  // 0..7
#pragma unroll
    for (int r = 0; r < 32; r += 8)
        tile[tw + r][tx] = Uw[(size_t)(by + tw + r) * H_ + bx + tx];
    __syncthreads();
#pragma unroll
    for (int r = 0; r < 32; r += 8)
        g_UwT[(size_t)(bx + tw + r) * H_ + by + tx] = tile[tx][tw + r];
}

// ---------------------------------------------------------------------------
// Projection (TF32 MMA, 2-way split, 4 terms hh+hl+lh+ll): out = x@W^T + Ub + b
// M=131072, N=1024, K=512. Block tile 128x128, bk=32, 8 warps (4m x 2n).
// Only error source: lo representation (<=2^-22/element) -> ~4e-5 final.
// ---------------------------------------------------------------------------
__global__ __launch_bounds__(256) void proj_tf32_kernel(
    const float* __restrict__ x, const float* __restrict__ W,
    const float* __restrict__ Ub, const float* __restrict__ bvec,
    float* __restrict__ out)
{
    extern __shared__ float psm[];
    float* Axh = psm;                 // [128][PKP2] each
    float* Axl = Axh + 128 * PKP2;
    float* Bwh = Axl + 128 * PKP2;
    float* Bwl = Bwh + 128 * PKP2;

    const int tid  = threadIdx.x;
    const int lane = tid & 31;
    const int g    = lane >> 2;       // groupID 0..7
    const int tg   = lane & 3;        // thread-in-group 0..3
    const int wid  = tid >> 5;
    const int m0 = blockIdx.y * 128;
    const int n0 = blockIdx.x * 128;
    const int wm = (wid & 3) * 32;    // warp m offset (32 rows)
    const int wn = (wid >> 2) * 64;   // warp n offset (64 cols)

    float D[2][8][4];
#pragma unroll
    for (int i = 0; i < 2; i++)
#pragma unroll
        for (int j = 0; j < 8; j++)
#pragma unroll
            for (int k = 0; k < 4; k++) D[i][j][k] = 0.f;

    for (int kb = 0; kb < I_; kb += 32) {
        __syncthreads();   // protect smem overwrite vs previous iter's reads
#pragma unroll
        for (int l = 0; l < 4; l++) {
            int idx = tid + l * 256;     // 0..1023
            int row = idx >> 3;          // 0..127
            int c4  = (idx & 7) << 2;    // 0..28
            float4 xv = *(const float4*)(x + (size_t)(m0 + row) * I_ + kb + c4);
            split4(Axh + row * PKP2 + c4, Axl + row * PKP2 + c4, xv);
            float4 wv = *(const float4*)(W + (size_t)(n0 + row) * I_ + kb + c4);
            split4(Bwh + row * PKP2 + c4, Bwl + row * PKP2 + c4, wv);
        }
        __syncthreads();

#pragma unroll
        for (int kc = 0; kc < 4; kc++) {        // 4 x k8 chunks
            const int col = kc * 8 + tg;
            uint32_t ah[2][4], al[2][4];
#pragma unroll
            for (int mt = 0; mt < 2; mt++) {
                int r = wm + mt * 16 + g;
                ah[mt][0] = __float_as_uint(Axh[r * PKP2 + col]);
                ah[mt][1] = __float_as_uint(Axh[(r + 8) * PKP2 + col]);
                ah[mt][2] = __float_as_uint(Axh[r * PKP2 + col + 4]);
                ah[mt][3] = __float_as_uint(Axh[(r + 8) * PKP2 + col + 4]);
                al[mt][0] = __float_as_uint(Axl[r * PKP2 + col]);
                al[mt][1] = __float_as_uint(Axl[(r + 8) * PKP2 + col]);
                al[mt][2] = __float_as_uint(Axl[r * PKP2 + col + 4]);
                al[mt][3] = __float_as_uint(Axl[(r + 8) * PKP2 + col + 4]);
            }
#pragma unroll
            for (int nt = 0; nt < 8; nt++) {
                int n = wn + nt * 8 + g;
                uint32_t bh[2], bl[2];
                bh[0] = __float_as_uint(Bwh[n * PKP2 + col]);
                bh[1] = __float_as_uint(Bwh[n * PKP2 + col + 4]);
                bl[0] = __float_as_uint(Bwl[n * PKP2 + col]);
                bl[1] = __float_as_uint(Bwl[n * PKP2 + col + 4]);
#pragma unroll
                for (int mt = 0; mt < 2; mt++) {
                    mma_tf32(D[mt][nt], ah[mt], bh);   // hh
                    mma_tf32(D[mt][nt], ah[mt], bl);   // hl
                    mma_tf32(D[mt][nt], al[mt], bh);   // lh
                    mma_tf32(D[mt][nt], al[mt], bl);   // ll
                }
            }
        }
    }

    // epilogue: + Ub + b (fragment rows: g, g+8; cols: 2*tg, 2*tg+1)
#pragma unroll
    for (int nt = 0; nt < 8; nt++) {
        int n = n0 + wn + nt * 8 + tg * 2;
        float ub0 = Ub[n]     + bvec[n];
        float ub1 = Ub[n + 1] + bvec[n + 1];
#pragma unroll
        for (int mt = 0; mt < 2; mt++) {
            int m = m0 + wm + mt * 16 + g;
            float2 v0 = make_float2(D[mt][nt][0] + ub0, D[mt][nt][1] + ub1);
            float2 v1 = make_float2(D[mt][nt][2] + ub0, D[mt][nt][3] + ub1);
            *(float2*)(out + (size_t)m * H_ + n)       = v0;
            *(float2*)(out + (size_t)(m + 8) * H_ + n) = v1;
        }
    }
}

// ---------------------------------------------------------------------------
// Persistent fp32 recurrence — EXACT R4-validated kernel (5.5e-6, ~4.85us/step).
//   out[b][t][n] += sum_k out[b][t-1][k] * Uw[n][k]
// ---------------------------------------------------------------------------
__global__ __launch_bounds__(256) void rnn_persistent_kernel(float* __restrict__ out)
{
    __shared__ float Ss[64][132];    // [b][k-slab], padded
    __shared__ float Us[128][64];    // [k-slab][n-tile]
    const int tid = threadIdx.x;
    const int bid = blockIdx.x;
    const int n0 = (bid & 15) * 64;
    const int k0 = (bid >> 4) * 128;
    const int ty = tid >> 4;         // 0..15 -> b-quad
    const int tx = tid & 15;         // 0..15 -> n-quad

    // Preload UwT slab (128 x 64 floats) once.
#pragma unroll
    for (int l = 0; l < 8; l++) {
        int idx = tid + l * 256;     // 0..2047
        int r  = idx >> 4;           // 0..127 (k)
        int c4 = (idx & 15) << 2;    // 0..60  (n)
        *(float4*)&Us[r][c4] =
            *(const float4*)(g_UwT + (size_t)(k0 + r) * H_ + n0 + c4);
    }
    __syncthreads();

    for (int t = 1; t < T_; t++) {
        const float* prev = out + (size_t)(t - 1) * H_ + k0;
#pragma unroll
        for (int l = 0; l < 8; l++) {
            int idx = tid + l * 256;   // 0..2047
            int b   = idx >> 5;        // 0..63
            int c4  = (idx & 31) << 2; // 0..124
            *(float4*)&Ss[b][c4] =
                *(const float4*)(prev + (size_t)b * BSTRIDE + c4);
        }
        __syncthreads();

        float acc[4][4];
#pragma unroll
        for (int i = 0; i < 4; i++)
#pragma unroll
            for (int j = 0; j < 4; j++) acc[i][j] = 0.f;

#pragma unroll 8
        for (int k = 0; k < 128; k++) {
            float4 bv = *(const float4*)&Us[k][tx * 4];
            float a0 = Ss[ty * 4 + 0][k];
            float a1 = Ss[ty * 4 + 1][k];
            float a2 = Ss[ty * 4 + 2][k];
            float a3 = Ss[ty * 4 + 3][k];
            acc[0][0] += a0 * bv.x; acc[0][1] += a0 * bv.y; acc[0][2] += a0 * bv.z; acc[0][3] += a0 * bv.w;
            acc[1][0] += a1 * bv.x; acc[1][1] += a1 * bv.y; acc[1][2] += a1 * bv.z; acc[1][3] += a1 * bv.w;
            acc[2][0] += a2 * bv.x; acc[2][1] += a2 * bv.y; acc[2][2] += a2 * bv.z; acc[2][3] += a2 * bv.w;
            acc[3][0] += a3 * bv.x; acc[3][1] += a3 * bv.y; acc[3][2] += a3 * bv.z; acc[3][3] += a3 * bv.w;
        }

#pragma unroll
        for (int i = 0; i < 4; i++) {
            float* dst = out + (size_t)(ty * 4 + i) * BSTRIDE
                             + (size_t)t * H_ + n0 + tx * 4;
            asm volatile("red.global.add.v4.f32 [%0], {%1,%2,%3,%4};"
                         :: "l"(dst), "f"(acc[i][0]), "f"(acc[i][1]),
                            "f"(acc[i][2]), "f"(acc[i][3])
                         : "memory");
        }

        if (t < T_ - 1) {
            __threadfence();
            if (tid == 0) {
                unsigned target = (unsigned)t * NBLK;
                atomicAdd(&g_bar, 1u);
                unsigned v;
                do {
                    asm volatile("ld.acquire.gpu.global.u32 %0, [%1];"
                                 : "=r"(v) : "l"(&g_bar));
                } while (v < target);
            }
            __syncthreads();
        }
    }
}

// ---------------------------------------------------------------------------
extern "C" void kernel_launch(void* const* d_in, const int* in_sizes, int n_in,
                              void* d_out, int out_size) {
    (void)in_sizes; (void)n_in; (void)out_size;
    const float* x   = (const float*)d_in[0];
    const float* W   = (const float*)d_in[1];
    const float* Uw  = (const float*)d_in[2];
    const float* Ub  = (const float*)d_in[3];
    const float* bv  = (const float*)d_in[4];
    float* out = (float*)d_out;

    const int proj_smem = 4 * 128 * PKP2 * 4;  // 73728 B
    cudaFuncSetAttribute(proj_tf32_kernel,
                         cudaFuncAttributeMaxDynamicSharedMemorySize, proj_smem);

    // 1) transpose Uw -> g_UwT and reset barrier counter (R4-validated)
    uw_transpose_kernel<<<dim3(H_ / 32, H_ / 32), 256>>>(Uw);

    // 2) wx = x @ W^T + Ub + b  (tf32 MMA, 4-term split — the experimental variable)
    proj_tf32_kernel<<<dim3(H_ / 128, MTOT / 128), 256, proj_smem>>>(
        x, W, Ub, bv, out);

    // 3) all 2047 recurrence steps, fp32 FFMA (R4-validated kernel)
    rnn_persistent_kernel<<<NBLK, 256>>>(out);
}

// round 12
// speedup vs baseline: 1.0426x; 1.0378x over previous
#include <cuda_runtime.h>
#include <cstdint>

#define B_ 64
#define T_ 2048
#define I_ 512
#define H_ 1024
#define MTOT (B_ * T_)
#define BSTRIDE ((size_t)T_ * H_)   // stride between batch rows in out
#define NBLK 128                    // persistent grid: 16 n-tiles x 8 k-slabs

// Scratch: Uw transposed to [k][n] (R4-validated).
__device__ float g_UwT[H_ * H_];
__device__ unsigned g_bar;          // grid-barrier arrival counter

// ---------------------------------------------------------------------------
// packed-fp32 helpers (sm_103a FFMA2 via PTX fma.rn.f32x2; exact IEEE RN
// per lane -> identical numerics to scalar FFMA in the same order)
// ---------------------------------------------------------------------------
__device__ __forceinline__ unsigned long long dup2(float x) {
    unsigned long long r; unsigned u = __float_as_uint(x);
    asm("mov.b64 %0, {%1, %2};" : "=l"(r) : "r"(u), "r"(u));
    return r;
}
__device__ __forceinline__ void fma2(unsigned long long& d,
                                     unsigned long long a, unsigned long long b) {
    asm("fma.rn.f32x2 %0, %1, %2, %0;" : "+l"(d) : "l"(a), "l"(b));
}
__device__ __forceinline__ float2 unpk(unsigned long long v) {
    unsigned lo, hi;
    asm("mov.b64 {%0, %1}, %2;" : "=r"(lo), "=r"(hi) : "l"(v));
    return make_float2(__uint_as_float(lo), __uint_as_float(hi));
}

// ---------------------------------------------------------------------------
// Transpose Uw[n][k] -> g_UwT[k][n]; also reset the grid barrier. (R4-validated)
// ---------------------------------------------------------------------------
__global__ __launch_bounds__(256) void uw_transpose_kernel(const float* __restrict__ Uw) {
    if (blockIdx.x == 0 && blockIdx.y == 0 && threadIdx.x == 0) g_bar = 0u;
    __shared__ float tile[32][33];
    const int bx = blockIdx.x * 32;
    const int by = blockIdx.y * 32;
    const int tx = threadIdx.x & 31;
    const int tw = threadIdx.x >> 5;
#pragma unroll
    for (int r = 0; r < 32; r += 8)
        tile[tw + r][tx] = Uw[(size_t)(by + tw + r) * H_ + bx + tx];
    __syncthreads();
#pragma unroll
    for (int r = 0; r < 32; r += 8)
        g_UwT[(size_t)(bx + tw + r) * H_ + by + tx] = tile[tx][tw + r];
}

// ---------------------------------------------------------------------------
// Projection (fp32 FFMA2): out[m][n] = sum_k x[m][k]*W[n][k] + Ub[n] + b[n]
// Identical tiling/order to the R4-validated fp32 proj; inner loop packed.
// ---------------------------------------------------------------------------
__global__ __launch_bounds__(256) void proj_kernel(
    const float* __restrict__ x, const float* __restrict__ W,
    const float* __restrict__ Ub, const float* __restrict__ bvec,
    float* __restrict__ out)
{
    __shared__ float As[16][128];
    __shared__ float Bs[16][128];
    const int tid = threadIdx.x;
    const int m0 = blockIdx.y * 128;
    const int n0 = blockIdx.x * 128;
    const int ty = tid >> 4;   // 0..15
    const int tx = tid & 15;   // 0..15

    unsigned long long acc[8][4];   // 8 m-rows x 4 n-pairs (8 n-cols)
#pragma unroll
    for (int i = 0; i < 8; i++)
#pragma unroll
        for (int j = 0; j < 4; j++) acc[i][j] = 0ull;

    for (int kb = 0; kb < I_; kb += 16) {
#pragma unroll
        for (int l = 0; l < 2; l++) {
            int idx = tid + l * 256;        // 0..511
            int row = idx >> 2;             // 0..127
            int c4  = (idx & 3) << 2;       // 0,4,8,12
            float4 av = *(const float4*)(x + (size_t)(m0 + row) * I_ + kb + c4);
            As[c4 + 0][row] = av.x; As[c4 + 1][row] = av.y;
            As[c4 + 2][row] = av.z; As[c4 + 3][row] = av.w;
            float4 wv = *(const float4*)(W + (size_t)(n0 + row) * I_ + kb + c4);
            Bs[c4 + 0][row] = wv.x; Bs[c4 + 1][row] = wv.y;
            Bs[c4 + 2][row] = wv.z; Bs[c4 + 3][row] = wv.w;
        }
        __syncthreads();
#pragma unroll
        for (int k = 0; k < 16; k++) {
            float4 a0 = *(const float4*)&As[k][ty * 8];
            float4 a1 = *(const float4*)&As[k][ty * 8 + 4];
            ulonglong2 b01 = *(const ulonglong2*)&Bs[k][tx * 8];      // n-pairs 0,1
            ulonglong2 b23 = *(const ulonglong2*)&Bs[k][tx * 8 + 4];  // n-pairs 2,3
            unsigned long long ad[8];
            ad[0] = dup2(a0.x); ad[1] = dup2(a0.y); ad[2] = dup2(a0.z); ad[3] = dup2(a0.w);
            ad[4] = dup2(a1.x); ad[5] = dup2(a1.y); ad[6] = dup2(a1.z); ad[7] = dup2(a1.w);
#pragma unroll
            for (int i = 0; i < 8; i++) {
                fma2(acc[i][0], ad[i], b01.x);
                fma2(acc[i][1], ad[i], b01.y);
                fma2(acc[i][2], ad[i], b23.x);
                fma2(acc[i][3], ad[i], b23.y);
            }
        }
        __syncthreads();
    }

    float ubb[8];
#pragma unroll
    for (int j = 0; j < 8; j++) {
        int n = n0 + tx * 8 + j;
        ubb[j] = Ub[n] + bvec[n];
    }
#pragma unroll
    for (int i = 0; i < 8; i++) {
        float2 p0 = unpk(acc[i][0]);
        float2 p1 = unpk(acc[i][1]);
        float2 p2 = unpk(acc[i][2]);
        float2 p3 = unpk(acc[i][3]);
        float* dst = out + (size_t)(m0 + ty * 8 + i) * H_ + n0 + tx * 8;
        float4 v0 = make_float4(p0.x + ubb[0], p0.y + ubb[1],
                                p1.x + ubb[2], p1.y + ubb[3]);
        float4 v1 = make_float4(p2.x + ubb[4], p2.y + ubb[5],
                                p3.x + ubb[6], p3.y + ubb[7]);
        *(float4*)dst       = v0;
        *(float4*)(dst + 4) = v1;
    }
}

// ---------------------------------------------------------------------------
// Persistent fp32 recurrence (FFMA2) — R4-validated structure & accumulation
// order; inner loop packed. out[b][t][n] += sum_k out[b][t-1][k] * Uw[n][k]
// ---------------------------------------------------------------------------
__global__ __launch_bounds__(256) void rnn_persistent_kernel(float* __restrict__ out)
{
    __shared__ float Ss[64][132];    // [b][k-slab], padded (rows 8B-aligned)
    __shared__ float Us[128][64];    // [k-slab][n-tile]
    const int tid = threadIdx.x;
    const int bid = blockIdx.x;
    const int n0 = (bid & 15) * 64;
    const int k0 = (bid >> 4) * 128;
    const int ty = tid >> 4;         // 0..15 -> b-quad
    const int tx = tid & 15;         // 0..15 -> n-quad

    // Preload UwT slab (128 x 64 floats) once.
#pragma unroll
    for (int l = 0; l < 8; l++) {
        int idx = tid + l * 256;     // 0..2047
        int r  = idx >> 4;           // 0..127 (k)
        int c4 = (idx & 15) << 2;    // 0..60  (n)
        *(float4*)&Us[r][c4] =
            *(const float4*)(g_UwT + (size_t)(k0 + r) * H_ + n0 + c4);
    }
    __syncthreads();

    for (int t = 1; t < T_; t++) {
        const float* prev = out + (size_t)(t - 1) * H_ + k0;
#pragma unroll
        for (int l = 0; l < 8; l++) {
            int idx = tid + l * 256;   // 0..2047
            int b   = idx >> 5;        // 0..63
            int c4  = (idx & 31) << 2; // 0..124
            *(float4*)&Ss[b][c4] =
                *(const float4*)(prev + (size_t)b * BSTRIDE + c4);
        }
        __syncthreads();

        unsigned long long acc[4][2];   // 4 b-rows x 2 n-pairs (4 n-cols)
#pragma unroll
        for (int i = 0; i < 4; i++) { acc[i][0] = 0ull; acc[i][1] = 0ull; }

#pragma unroll 8
        for (int k = 0; k < 128; k += 2) {
            ulonglong2 bb0 = *(const ulonglong2*)&Us[k][tx * 4];     // k:   n-pairs
            ulonglong2 bb1 = *(const ulonglong2*)&Us[k + 1][tx * 4]; // k+1: n-pairs
            float2 a0 = *(const float2*)&Ss[ty * 4 + 0][k];
            float2 a1 = *(const float2*)&Ss[ty * 4 + 1][k];
            float2 a2 = *(const float2*)&Ss[ty * 4 + 2][k];
            float2 a3 = *(const float2*)&Ss[ty * 4 + 3][k];
            // k term, then k+1 term — same per-element order as scalar R4
            unsigned long long d;
            d = dup2(a0.x); fma2(acc[0][0], d, bb0.x); fma2(acc[0][1], d, bb0.y);
            d = dup2(a0.y); fma2(acc[0][0], d, bb1.x); fma2(acc[0][1], d, bb1.y);
            d = dup2(a1.x); fma2(acc[1][0], d, bb0.x); fma2(acc[1][1], d, bb0.y);
            d = dup2(a1.y); fma2(acc[1][0], d, bb1.x); fma2(acc[1][1], d, bb1.y);
            d = dup2(a2.x); fma2(acc[2][0], d, bb0.x); fma2(acc[2][1], d, bb0.y);
            d = dup2(a2.y); fma2(acc[2][0], d, bb1.x); fma2(acc[2][1], d, bb1.y);
            d = dup2(a3.x); fma2(acc[3][0], d, bb0.x); fma2(acc[3][1], d, bb0.y);
            d = dup2(a3.y); fma2(acc[3][0], d, bb1.x); fma2(acc[3][1], d, bb1.y);
        }

#pragma unroll
        for (int i = 0; i < 4; i++) {
            float2 p0 = unpk(acc[i][0]);
            float2 p1 = unpk(acc[i][1]);
            float* dst = out + (size_t)(ty * 4 + i) * BSTRIDE
                             + (size_t)t * H_ + n0 + tx * 4;
            asm volatile("red.global.add.v4.f32 [%0], {%1,%2,%3,%4};"
                         :: "l"(dst), "f"(p0.x), "f"(p0.y), "f"(p1.x), "f"(p1.y)
                         : "memory");
        }

        if (t < T_ - 1) {
            __threadfence();
            __syncthreads();   // join ALL warps' REDs before tid0 arrives
            if (tid == 0) {
                unsigned target = (unsigned)t * NBLK;
                atomicAdd(&g_bar, 1u);
                unsigned v;
                do {
                    asm volatile("ld.acquire.gpu.global.u32 %0, [%1];"
                                 : "=r"(v) : "l"(&g_bar));
                } while (v < target);
            }
            __syncthreads();
        }
    }
}

// ---------------------------------------------------------------------------
extern "C" void kernel_launch(void* const* d_in, const int* in_sizes, int n_in,
                              void* d_out, int out_size) {
    (void)in_sizes; (void)n_in; (void)out_size;
    const float* x   = (const float*)d_in[0];
    const float* W   = (const float*)d_in[1];
    const float* Uw  = (const float*)d_in[2];
    const float* Ub  = (const float*)d_in[3];
    const float* bv  = (const float*)d_in[4];
    float* out = (float*)d_out;

    // 1) transpose Uw -> g_UwT and reset barrier counter
    uw_transpose_kernel<<<dim3(H_ / 32, H_ / 32), 256>>>(Uw);

    // 2) wx = x @ W^T + Ub + b   (fp32 FFMA2)
    proj_kernel<<<dim3(H_ / 128, MTOT / 128), 256>>>(x, W, Ub, bv, out);

    // 3) all 2047 recurrence steps, fp32 FFMA2 persistent kernel
    rnn_persistent_kernel<<<NBLK, 256>>>(out);
}